// round 9
// baseline (speedup 1.0000x reference)
#include <cuda_runtime.h>

// DynamicPatching: B=32, C=64, T=8192, S=64.
// out[b][s][c][p] = (p < len_bs) ? tensor[b][c][start_bs + p] : 0
// Output (B, S, C, max_len) row-major.
//
// LDG.128 + STG.128 both sides. Source misalignment handled by aligned-pair
// + shift-select with the 4-way shift switch HOISTED per row (shift is
// row-uniform), so the hot loops contain no branches/predicates. Rows are
// processed sequentially to keep registers <=32 (8 blocks/SM). Zero region
// is a pure STG.128 stream. ld.cs streams the input past L2; plain stores
// let L2 absorb the write stream.

#define PB 32
#define PC 64
#define PT 8192
#define PS 64

__device__ __forceinline__ float ldcs(const float* p) {
    float v;
    asm volatile("ld.global.cs.f32 %0, [%1];" : "=f"(v) : "l"(p));
    return v;
}
__device__ __forceinline__ float4 ld4cs(const float4* p) {
    float4 v;
    asm volatile("ld.global.cs.v4.f32 {%0,%1,%2,%3}, [%4];"
                 : "=f"(v.x), "=f"(v.y), "=f"(v.z), "=f"(v.w) : "l"(p));
    return v;
}
__device__ __forceinline__ void st4(float* p, float4 v) {
    *reinterpret_cast<float4*>(p) = v;
}

__global__ void __launch_bounds__(256, 8)
dynamic_patching_kernel(const float* __restrict__ tensor,
                        const int*   __restrict__ cps,   // (B, S+1) int32
                        float*       __restrict__ out,
                        int max_len)
{
    // 2 blocks per (b,s): each block covers 32 of the 64 channels.
    const int bs   = blockIdx.x >> 1;
    const int half = blockIdx.x & 1;
    const int b    = bs >> 6;            // / PS
    const int s    = bs & (PS - 1);      // % PS

    const int start = __ldg(cps + b * (PS + 1) + s);
    const int len   = __ldg(cps + b * (PS + 1) + s + 1) - start;

    const int wid  = threadIdx.x >> 5;   // 0..7
    const int lane = threadIdx.x & 31;
    const int c0   = half * 32 + wid * 4;          // warp's first channel

    const float* __restrict__ srcW =
        tensor + ((size_t)b * PC + c0) * PT + start;
    const long long dbase =
        ((long long)bs * PC + c0) * (long long)max_len;

    #pragma unroll 1
    for (int r = 0; r < 4; ++r) {
        const float* __restrict__ src = srcW + r * PT;
        const long long drow = dbase + (long long)r * max_len;
        float* __restrict__ dst = out + drow;

        const int p0   = (int)((4 - ((int)(drow & 3))) & 3);
        const int nch  = (max_len - p0) >> 2;         // aligned chunks in row
        const int vlen = len - p0;
        int kfull      = (vlen > 0) ? (vlen >> 2) : 0;      // full-valid chunks
        const int kz   = (vlen > 0) ? ((vlen + 3) >> 2) : 0; // first pure-zero
        const int a    = (start + p0) & 3;

        // The hi load of the last full chunk may read 2 floats past len;
        // only on the global last row can this cross the allocation. Demote
        // that one chunk to the scalar cleanup path.
        if (a && kfull > 0 &&
            b == PB - 1 && (c0 + r) == PC - 1 && s == PS - 1)
            kfull -= 1;

        const float4* __restrict__ ab =
            reinterpret_cast<const float4*>(src + p0 - a);

        // Head scalars (< p0 <= 3).
        if (lane < p0)
            dst[lane] = (lane < len) ? ldcs(src + lane) : 0.0f;

        // Full-valid vector body: shift switch hoisted out of the loop.
        if (a == 0) {
            for (int k = lane; k < kfull; k += 32)
                st4(dst + p0 + (k << 2), ld4cs(ab + k));
        } else if (a == 1) {
            for (int k = lane; k < kfull; k += 32) {
                const float4 lo = ld4cs(ab + k);
                const float4 hi = ld4cs(ab + k + 1);
                st4(dst + p0 + (k << 2), make_float4(lo.y, lo.z, lo.w, hi.x));
            }
        } else if (a == 2) {
            for (int k = lane; k < kfull; k += 32) {
                const float4 lo = ld4cs(ab + k);
                const float4 hi = ld4cs(ab + k + 1);
                st4(dst + p0 + (k << 2), make_float4(lo.z, lo.w, hi.x, hi.y));
            }
        } else {
            for (int k = lane; k < kfull; k += 32) {
                const float4 lo = ld4cs(ab + k);
                const float4 hi = ld4cs(ab + k + 1);
                st4(dst + p0 + (k << 2), make_float4(lo.w, hi.x, hi.y, hi.z));
            }
        }

        // Scalar cleanup: chunks [kfull, kz) — boundary chunk plus (rarely)
        // the demoted last chunk. At most 8 elements; predicated.
        {
            const int ncl = (kz - kfull) << 2;      // 0, 4 or 8 elements
            if (lane < ncl) {
                const int p = p0 + (kfull << 2) + lane;
                if (p < max_len)
                    dst[p] = (p < len) ? ldcs(src + p) : 0.0f;
            }
        }

        // Pure-zero vector body: store-only stream.
        const float4 z4 = make_float4(0.0f, 0.0f, 0.0f, 0.0f);
        for (int k = kz + lane; k < nch; k += 32)
            st4(dst + p0 + (k << 2), z4);

        // Tail scalars (< 4), may be valid or pad.
        {
            const int ts = p0 + (nch << 2);
            const int p  = ts + lane;
            if (p < max_len)
                dst[p] = (p < len) ? ldcs(src + p) : 0.0f;
        }
    }
}

extern "C" void kernel_launch(void* const* d_in, const int* in_sizes, int n_in,
                              void* d_out, int out_size)
{
    const float* tensor = (const float*)d_in[0];
    const int*   cps    = (const int*)d_in[1];
    float*       out    = (float*)d_out;

    const int max_len = out_size / (PB * PS * PC);

    dynamic_patching_kernel<<<PB * PS * 2, 256>>>(tensor, cps, out, max_len);
}

// round 10
// speedup vs baseline: 1.2579x; 1.2579x over previous
#include <cuda_runtime.h>

// DynamicPatching: B=32, C=64, T=8192, S=64.
// out[b][s][c][p] = (p < len_bs) ? tensor[b][c][start_bs + p] : 0
// Output (B, S, C, max_len) row-major.
//
// R4 champion structure (warp owns 4 rows; two-phase: 16 loads batched before
// 4 STG.128) with: chunk-level classification (full -> unpredicated loads,
// pad -> store-only, boundary -> predicated), 32B-aligned warp stores, and
// launch_bounds(256,6) for >=6 blocks/SM.

#define PB 32
#define PC 64
#define PT 8192
#define PS 64

__device__ __forceinline__ float ldcs(const float* p) {
    float v;
    asm volatile("ld.global.cs.f32 %0, [%1];" : "=f"(v) : "l"(p));
    return v;
}
__device__ __forceinline__ void stcs4(float* p, float4 v) {
    asm volatile("st.global.cs.v4.f32 [%0], {%1,%2,%3,%4};"
                 :: "l"(p), "f"(v.x), "f"(v.y), "f"(v.z), "f"(v.w) : "memory");
}

__global__ void __launch_bounds__(256, 6)
dynamic_patching_kernel(const float* __restrict__ tensor,
                        const int*   __restrict__ cps,   // (B, S+1) int32
                        float*       __restrict__ out,
                        int max_len)
{
    // 2 blocks per (b,s): each block covers 32 of the 64 channels.
    const int bs   = blockIdx.x >> 1;
    const int half = blockIdx.x & 1;
    const int b    = bs >> 6;            // / PS
    const int s    = bs & (PS - 1);      // % PS

    const int start = __ldg(cps + b * (PS + 1) + s);
    const int len   = __ldg(cps + b * (PS + 1) + s + 1) - start;

    const int wid  = threadIdx.x >> 5;   // 0..7
    const int lane = threadIdx.x & 31;
    const int c0   = half * 32 + wid * 4;          // warp's first channel

    // All offsets fit in int32 (tensor 16.8M elems, out <= ~29M elems).
    const float* __restrict__ srcB = tensor + ((b * PC + c0) << 13) + start;
    const int dbase = (bs * PC + c0) * max_len;
    float* __restrict__ dstB = out + dbase;

    // Per-row: p0 = first 32B-aligned offset; nv = # 4-float chunks;
    // kf = # fully-valid chunks.
    int p0[4], nv[4], kf[4];
    int nvmax = 0;
    #pragma unroll
    for (int r = 0; r < 4; ++r) {
        p0[r] = (8 - ((dbase + r * max_len) & 7)) & 7;
        nv[r] = (max_len - p0[r]) >> 2;
        const int lp = len - p0[r];
        kf[r] = (lp > 0) ? (lp >> 2) : 0;
        nvmax = max(nvmax, nv[r]);
    }

    // Heads (< 8 elems) and tails (< 4 elems), hoisted.
    #pragma unroll
    for (int r = 0; r < 4; ++r) {
        const int drow = r * max_len;
        if (lane < p0[r])
            dstB[drow + lane] = (lane < len) ? ldcs(srcB + (r << 13) + lane) : 0.0f;
        const int p = p0[r] + (nv[r] << 2) + lane;
        if (p < max_len)
            dstB[drow + p] = (p < len) ? ldcs(srcB + (r << 13) + p) : 0.0f;
    }

    // Hot loop. Phase 1: up to 16 independent loads across 4 rows.
    //   k <  kf[r]          : full chunk, 4 unpredicated ld.cs
    //   p <  len (k == kf)  : boundary chunk, per-element predicated
    //   else                : pad chunk, v stays zero (no loads, no compares)
    // Phase 2: 4 STG.128 (warp-level 512B stores, 32B-aligned).
    for (int kb = 0; kb < nvmax; kb += 32) {
        const int k = kb + lane;
        float4 v[4];

        #pragma unroll
        for (int r = 0; r < 4; ++r) {
            v[r] = make_float4(0.0f, 0.0f, 0.0f, 0.0f);
            if (k < nv[r]) {
                const int p = p0[r] + (k << 2);
                const float* sp = srcB + (r << 13) + p;
                if (k < kf[r]) {
                    v[r].x = ldcs(sp + 0);
                    v[r].y = ldcs(sp + 1);
                    v[r].z = ldcs(sp + 2);
                    v[r].w = ldcs(sp + 3);
                } else if (p < len) {
                    v[r].x = ldcs(sp + 0);
                    if (p + 1 < len) v[r].y = ldcs(sp + 1);
                    if (p + 2 < len) v[r].z = ldcs(sp + 2);
                    if (p + 3 < len) v[r].w = ldcs(sp + 3);
                }
            }
        }

        #pragma unroll
        for (int r = 0; r < 4; ++r) {
            if (k < nv[r])
                stcs4(dstB + r * max_len + p0[r] + (k << 2), v[r]);
        }
    }
}

extern "C" void kernel_launch(void* const* d_in, const int* in_sizes, int n_in,
                              void* d_out, int out_size)
{
    const float* tensor = (const float*)d_in[0];
    const int*   cps    = (const int*)d_in[1];
    float*       out    = (float*)d_out;

    const int max_len = out_size / (PB * PS * PC);

    dynamic_patching_kernel<<<PB * PS * 2, 256>>>(tensor, cps, out, max_len);
}